// round 11
// baseline (speedup 1.0000x reference)
#include <cuda_runtime.h>
#include <cuda_fp16.h>
#include <cstdint>

#define N_EXPERTS 16
#define D_MODEL   1024
#define D_FF      2816
#define N_TOKENS  8192
#define TOP_K     2
#define A_TOTAL   (N_TOKENS * TOP_K)

#define BM 128
#define BK 32
#define BN 128

#define A_STH 40                   // A smem row stride (halves): ldmatrix conflict-free
#define B_STH 136                  // B smem row stride (halves): ldmatrix.trans conflict-free
#define A_STAGE_H (BM * A_STH)     // 5120 halves = 10240 B
#define B_STAGE_H (BK * B_STH)     // 4352 halves =  8704 B

#define MAX_SLOTS  (A_TOTAL + N_EXPERTS * BM)  // 18432
#define MAX_MTILES (MAX_SLOTS / BM)            // 144

// ---------------- scratch (device globals) ----------------
__device__ int    g_perm[MAX_SLOTS];
__device__ float  g_wgt[MAX_SLOTS];
__device__ int    g_offsets[N_EXPERTS];
__device__ int    g_tile_expert[MAX_MTILES];
__device__ __half g_Xh[(size_t)N_TOKENS * D_MODEL];            // fp16 x
__device__ __half g_Hh[(size_t)MAX_SLOTS * D_FF];              // fp16 SwiGLU activations
__device__ __half g_W1h[(size_t)N_EXPERTS * D_MODEL * D_FF];   // fp16 weights
__device__ __half g_W2h[(size_t)N_EXPERTS * D_MODEL * D_FF];
__device__ __half g_W3h[(size_t)N_EXPERTS * D_FF * D_MODEL];

// ---------------- helpers ----------------
__device__ __forceinline__ void mma16(float* c, const uint32_t* a, const uint32_t* b) {
    asm("mma.sync.aligned.m16n8k16.row.col.f32.f16.f16.f32 "
        "{%0,%1,%2,%3}, {%4,%5,%6,%7}, {%8,%9}, {%0,%1,%2,%3};\n"
        : "+f"(c[0]), "+f"(c[1]), "+f"(c[2]), "+f"(c[3])
        : "r"(a[0]), "r"(a[1]), "r"(a[2]), "r"(a[3]),
          "r"(b[0]), "r"(b[1]));
}
__device__ __forceinline__ void ldsm4(uint32_t* r, uint32_t addr) {
    asm volatile("ldmatrix.sync.aligned.m8n8.x4.shared.b16 {%0,%1,%2,%3}, [%4];"
                 : "=r"(r[0]), "=r"(r[1]), "=r"(r[2]), "=r"(r[3]) : "r"(addr));
}
__device__ __forceinline__ void ldsm4t(uint32_t* r, uint32_t addr) {
    asm volatile("ldmatrix.sync.aligned.m8n8.x4.trans.shared.b16 {%0,%1,%2,%3}, [%4];"
                 : "=r"(r[0]), "=r"(r[1]), "=r"(r[2]), "=r"(r[3]) : "r"(addr));
}
__device__ __forceinline__ float silu_f(float x) { return x / (1.0f + __expf(-x)); }
__device__ __forceinline__ uint32_t smem_u32(const void* p) {
    return (uint32_t)__cvta_generic_to_shared(p);
}
__device__ __forceinline__ void cp16(uint32_t dst, const void* src) {
    asm volatile("cp.async.cg.shared.global [%0], [%1], 16;" :: "r"(dst), "l"(src));
}
__device__ __forceinline__ void cp16_pred(uint32_t dst, const void* src, int valid) {
    int sz = valid ? 16 : 0;   // sz=0 zero-fills the 16B destination
    asm volatile("cp.async.cg.shared.global [%0], [%1], 16, %2;"
                 :: "r"(dst), "l"(src), "r"(sz));
}
#define CP_COMMIT() asm volatile("cp.async.commit_group;" ::: "memory")
#define CP_WAIT1()  asm volatile("cp.async.wait_group 1;"  ::: "memory")

// ---------------- launch 1: convert everything to fp16 + zero output ----------------
#define WU ((size_t)N_EXPERTS * D_MODEL * D_FF / 8)   // 5,767,168 units of 8 floats
#define XU ((size_t)N_TOKENS * D_MODEL / 8)           // 1,048,576
#define CVT_UNITS (3 * WU + 2 * XU)

__device__ __forceinline__ void cvt8(const float4* __restrict__ src, __half* __restrict__ dst, size_t u) {
    float4 a = src[2 * u], b = src[2 * u + 1];
    __half2 h[4];
    h[0] = __floats2half2_rn(a.x, a.y);
    h[1] = __floats2half2_rn(a.z, a.w);
    h[2] = __floats2half2_rn(b.x, b.y);
    h[3] = __floats2half2_rn(b.z, b.w);
    *(uint4*)(dst + 8 * u) = *(uint4*)h;
}

__global__ void cvt_all_kernel(const float4* __restrict__ w1, const float4* __restrict__ w2,
                               const float4* __restrict__ w3, const float4* __restrict__ x,
                               float4* __restrict__ out) {
    size_t i = (size_t)blockIdx.x * blockDim.x + threadIdx.x;
    if (i < WU)                cvt8(w1, g_W1h, i);
    else if (i < 2 * WU)       cvt8(w2, g_W2h, i - WU);
    else if (i < 3 * WU)       cvt8(w3, g_W3h, i - 2 * WU);
    else if (i < 3 * WU + XU)  cvt8(x,  g_Xh,  i - 3 * WU);
    else if (i < CVT_UNITS) {
        size_t u = i - 3 * WU - XU;
        out[2 * u]     = make_float4(0.f, 0.f, 0.f, 0.f);
        out[2 * u + 1] = make_float4(0.f, 0.f, 0.f, 0.f);
    }
}

// ---------------- launch 2: count + scan + perm init (single block) ----------------
__global__ void scan_count_kernel(const int* __restrict__ eidx) {
    __shared__ int hist[8][N_EXPERTS];
    const int tid = threadIdx.x;
    const int wid = tid >> 5;
    if (tid < 128) ((int*)hist)[tid] = 0;
    for (int i = tid; i < MAX_SLOTS; i += 256) g_perm[i] = -1;
    __syncthreads();
    const int4* e4 = (const int4*)eidx;
    for (int i = tid; i < A_TOTAL / 4; i += 256) {
        int4 e = e4[i];
        atomicAdd(&hist[wid][e.x], 1);
        atomicAdd(&hist[wid][e.y], 1);
        atomicAdd(&hist[wid][e.z], 1);
        atomicAdd(&hist[wid][e.w], 1);
    }
    __syncthreads();
    if (tid == 0) {
        for (int i = 0; i < MAX_MTILES; i++) g_tile_expert[i] = -1;
        int acc = 0;
        for (int e = 0; e < N_EXPERTS; e++) {
            int cnt = 0;
            for (int w = 0; w < 8; w++) cnt += hist[w][e];
            g_offsets[e] = acc;
            int nt = (cnt + BM - 1) / BM;
            int t0 = acc / BM;
            for (int i = 0; i < nt; i++) g_tile_expert[t0 + i] = e;
            acc += nt * BM;
        }
    }
}

// ---------------- launch 3: scatter ----------------
__global__ void scatter_kernel(const int* __restrict__ eidx,
                               const float* __restrict__ ew) {
    int i = blockIdx.x * blockDim.x + threadIdx.x;
    if (i < A_TOTAL) {
        int e = eidx[i];
        int p = atomicAdd(&g_offsets[e], 1);
        g_perm[p] = i / TOP_K;
        g_wgt[p]  = ew[i];
    }
}

// ---------------- launch 4: GEMM1: H = silu(X@W1) * (X@W2), fp16 MMA ----------------
// grid (D_FF/BN=22, 144), 512 thr (16 warps). Warps 4(m) x 4(n); warp tile 32x32.
// 3-stage cp.async pipeline, ONE __syncthreads per kt.
__global__ void __launch_bounds__(512)
gemm1_kernel() {
    const int mt = blockIdx.y;
    const int e  = g_tile_expert[mt];
    if (e < 0) return;
    const int nb   = blockIdx.x * BN;
    const int row0 = mt * BM;

    extern __shared__ __half smem[];
    __half* sA  = smem;                       // 3 * A_STAGE_H
    __half* sB1 = sA  + 3 * A_STAGE_H;        // 3 * B_STAGE_H
    __half* sB2 = sB1 + 3 * B_STAGE_H;

    const int tid  = threadIdx.x;
    const int lane = tid & 31;
    const int wid  = tid >> 5;
    const int wm   = wid >> 2;      // 0..3
    const int wn   = wid & 3;       // 0..3
    const int m0   = wm * 32;
    const int nG   = wn * 32;
    const int g    = lane >> 2;
    const int t    = lane & 3;

    // A cp.async loader: 1 task/thread: m = tid>>2 (0..127), 16B quad kq = tid&3
    const int mA = tid >> 2, kqA = tid & 3;
    const int tok = g_perm[row0 + mA];
    const int av  = (tok >= 0);
    const __half* apg = g_Xh + (size_t)(tok < 0 ? 0 : tok) * D_MODEL + kqA * 8;
    const uint32_t dA = smem_u32(sA + mA * A_STH + kqA * 8);
    // B loaders: 1 task/thread each: k = tid>>4 (0..31), 16B quad nq = tid&15
    const int kB = tid >> 4, nqB = tid & 15;
    const __half* b1g = g_W1h + (size_t)e * D_MODEL * D_FF + (size_t)kB * D_FF + nb + nqB * 8;
    const __half* b2g = g_W2h + (size_t)e * D_MODEL * D_FF + (size_t)kB * D_FF + nb + nqB * 8;
    const uint32_t dB1 = smem_u32(sB1 + kB * B_STH + nqB * 8);
    const uint32_t dB2 = smem_u32(sB2 + kB * B_STH + nqB * 8);

    // ldmatrix lane offsets
    const int laR = (lane & 7) + 8 * ((lane >> 3) & 1);   // row within 16
    const int laK = 8 * (lane >> 4);                      // k-half select
    const uint32_t aoff  = smem_u32(sA)  + ((m0 + laR) * A_STH + laK) * 2;
    const uint32_t b1off = smem_u32(sB1) + (laR * B_STH + nG + laK) * 2;
    const uint32_t b2off = smem_u32(sB2) + (laR * B_STH + nG + laK) * 2;

    const int KT = D_MODEL / BK;   // 32

    auto issue = [&](int kt, int s) {
        if (kt < KT) {
            const int kg = kt * BK;
            cp16_pred(dA + s * A_STAGE_H * 2, apg + kg, av);
            cp16(dB1 + s * B_STAGE_H * 2, b1g + (size_t)kg * D_FF);
            cp16(dB2 + s * B_STAGE_H * 2, b2g + (size_t)kg * D_FF);
        }
        CP_COMMIT();
    };

    float accg[2][4][4] = {};
    float accv[2][4][4] = {};

    issue(0, 0); issue(1, 1);

    int s = 0, s2 = 2;   // s: compute stage, s2: stage to fill with kt+2
    for (int kt = 0; kt < KT; kt++) {
        CP_WAIT1();
        __syncthreads();
        issue(kt + 2, s2);   // writes stage (kt-1)%3: all warps finished it pre-sync

        const uint32_t aS  = aoff  + s * A_STAGE_H * 2;
        const uint32_t b1S = b1off + s * B_STAGE_H * 2;
        const uint32_t b2S = b2off + s * B_STAGE_H * 2;

#pragma unroll
        for (int kf = 0; kf < 2; kf++) {
            uint32_t af[2][4];
            ldsm4(af[0], aS + kf * 32);
            ldsm4(af[1], aS + kf * 32 + 16 * A_STH * 2);
#pragma unroll
            for (int nj = 0; nj < 2; nj++) {
                uint32_t bb1[4], bb2[4];
                ldsm4t(bb1, b1S + kf * 16 * B_STH * 2 + nj * 32);
                ldsm4t(bb2, b2S + kf * 16 * B_STH * 2 + nj * 32);
#pragma unroll
                for (int mi = 0; mi < 2; mi++) {
                    mma16(accg[mi][2 * nj],     af[mi], bb1);
                    mma16(accg[mi][2 * nj + 1], af[mi], bb1 + 2);
                    mma16(accv[mi][2 * nj],     af[mi], bb2);
                    mma16(accv[mi][2 * nj + 1], af[mi], bb2 + 2);
                }
            }
        }
        if (++s == 3) s = 0;
        if (++s2 == 3) s2 = 0;
    }

    // epilogue: SwiGLU -> g_Hh (fp16)
#pragma unroll
    for (int mi = 0; mi < 2; mi++) {
        const int r = m0 + mi * 16 + g;
        const size_t h0 = (size_t)(row0 + r)     * D_FF;
        const size_t h8 = (size_t)(row0 + r + 8) * D_FF;
#pragma unroll
        for (int ni = 0; ni < 4; ni++) {
            const int c = nb + nG + ni * 8 + 2 * t;
            *(__half2*)&g_Hh[h0 + c] = __floats2half2_rn(
                silu_f(accg[mi][ni][0]) * accv[mi][ni][0],
                silu_f(accg[mi][ni][1]) * accv[mi][ni][1]);
            *(__half2*)&g_Hh[h8 + c] = __floats2half2_rn(
                silu_f(accg[mi][ni][2]) * accv[mi][ni][2],
                silu_f(accg[mi][ni][3]) * accv[mi][ni][3]);
        }
    }
}

// ---------------- launch 5: GEMM2: out += wgt * (H @ W3), fp16 MMA ----------------
// grid (D_MODEL/BN=8, 144), 256 thr, 2 CTAs/SM. Warps 2(m) x 4(n); warp tile 64x32.
// 3-stage cp.async pipeline, ONE __syncthreads per kt.
__global__ void __launch_bounds__(256, 2)
gemm2_kernel(float* __restrict__ out) {
    const int mt = blockIdx.y;
    const int e  = g_tile_expert[mt];
    if (e < 0) return;
    const int nb   = blockIdx.x * BN;
    const int row0 = mt * BM;

    extern __shared__ __half smem[];
    __half* sA = smem;                     // 3 * A_STAGE_H
    __half* sB = sA + 3 * A_STAGE_H;       // 3 * B_STAGE_H

    const int tid  = threadIdx.x;
    const int lane = tid & 31;
    const int wid  = tid >> 5;
    const int wm   = wid >> 2;      // 0..1
    const int wn   = wid & 3;       // 0..3
    const int m0   = wm * 64;
    const int nG   = wn * 32;
    const int g    = lane >> 2;
    const int t    = lane & 3;

    // A loader: 2 tasks: q = tid + 256j: m = q>>2, kq = q&3
    const __half* apg[2];
    uint32_t dA[2];
#pragma unroll
    for (int j = 0; j < 2; j++) {
        const int q = tid + 256 * j;
        const int m = q >> 2, kq = q & 3;
        apg[j] = g_Hh + (size_t)(row0 + m) * D_FF + kq * 8;
        dA[j]  = smem_u32(sA + m * A_STH + kq * 8);
    }
    // B loader: 2 tasks: q: k = q>>4, nq = q&15
    const __half* bg[2];
    uint32_t dB[2];
#pragma unroll
    for (int j = 0; j < 2; j++) {
        const int q = tid + 256 * j;
        const int k = q >> 4, nq = q & 15;
        bg[j] = g_W3h + (size_t)e * D_FF * D_MODEL + (size_t)k * D_MODEL + nb + nq * 8;
        dB[j] = smem_u32(sB + k * B_STH + nq * 8);
    }

    const int laR = (lane & 7) + 8 * ((lane >> 3) & 1);
    const int laK = 8 * (lane >> 4);
    const uint32_t aoff = smem_u32(sA) + ((m0 + laR) * A_STH + laK) * 2;
    const uint32_t boff = smem_u32(sB) + (laR * B_STH + nG + laK) * 2;

    const int KT = D_FF / BK;   // 88

    auto issue = [&](int kt, int s) {
        if (kt < KT) {
            const int kg = kt * BK;
#pragma unroll
            for (int j = 0; j < 2; j++) cp16(dA[j] + s * A_STAGE_H * 2, apg[j] + kg);
#pragma unroll
            for (int j = 0; j < 2; j++) cp16(dB[j] + s * B_STAGE_H * 2, bg[j] + (size_t)kg * D_MODEL);
        }
        CP_COMMIT();
    };

    float acc[4][4][4] = {};

    issue(0, 0); issue(1, 1);

    int s = 0, s2 = 2;
    for (int kt = 0; kt < KT; kt++) {
        CP_WAIT1();
        __syncthreads();
        issue(kt + 2, s2);

        const uint32_t aS = aoff + s * A_STAGE_H * 2;
        const uint32_t bS = boff + s * B_STAGE_H * 2;

#pragma unroll
        for (int kf = 0; kf < 2; kf++) {
            uint32_t af[4][4];
#pragma unroll
            for (int mi = 0; mi < 4; mi++)
                ldsm4(af[mi], aS + kf * 32 + mi * 16 * A_STH * 2);
#pragma unroll
            for (int nj = 0; nj < 2; nj++) {
                uint32_t bb[4];
                ldsm4t(bb, bS + kf * 16 * B_STH * 2 + nj * 32);
#pragma unroll
                for (int mi = 0; mi < 4; mi++) {
                    mma16(acc[mi][2 * nj],     af[mi], bb);
                    mma16(acc[mi][2 * nj + 1], af[mi], bb + 2);
                }
            }
        }
        if (++s == 3) s = 0;
        if (++s2 == 3) s2 = 0;
    }

    // epilogue: weighted scatter-add (exactly 2 commutative adds per token)
#pragma unroll
    for (int mi = 0; mi < 4; mi++) {
        const int r  = m0 + mi * 16 + g;
        const int s0 = row0 + r;
        const int s8 = s0 + 8;
        const int tk0 = g_perm[s0];
        const int tk8 = g_perm[s8];
        const float wt0 = (tk0 >= 0) ? g_wgt[s0] : 0.f;
        const float wt8 = (tk8 >= 0) ? g_wgt[s8] : 0.f;
#pragma unroll
        for (int ni = 0; ni < 4; ni++) {
            const int c = nb + nG + ni * 8 + 2 * t;
            if (tk0 >= 0) {
                atomicAdd(&out[(size_t)tk0 * D_MODEL + c    ], acc[mi][ni][0] * wt0);
                atomicAdd(&out[(size_t)tk0 * D_MODEL + c + 1], acc[mi][ni][1] * wt0);
            }
            if (tk8 >= 0) {
                atomicAdd(&out[(size_t)tk8 * D_MODEL + c    ], acc[mi][ni][2] * wt8);
                atomicAdd(&out[(size_t)tk8 * D_MODEL + c + 1], acc[mi][ni][3] * wt8);
            }
        }
    }
}

// ---------------- launch ----------------
extern "C" void kernel_launch(void* const* d_in, const int* in_sizes, int n_in,
                              void* d_out, int out_size) {
    const float* x    = (const float*)d_in[0];
    const int*   eidx = (const int*)  d_in[1];
    const float* ew   = (const float*)d_in[2];
    const float* w1   = (const float*)d_in[3];
    const float* w2   = (const float*)d_in[4];
    const float* w3   = (const float*)d_in[5];
    float* out = (float*)d_out;

    const int smem1 = 3 * (A_STAGE_H + 2 * B_STAGE_H) * 2;   // 82944 B -> 1 CTA/SM
    const int smem2 = 3 * (A_STAGE_H + B_STAGE_H) * 2;       // 56832 B -> 2 CTAs/SM
    static int attr_done = 0;
    if (!attr_done) {
        cudaFuncSetAttribute(gemm1_kernel, cudaFuncAttributeMaxDynamicSharedMemorySize, smem1);
        cudaFuncSetAttribute(gemm2_kernel, cudaFuncAttributeMaxDynamicSharedMemorySize, smem2);
        attr_done = 1;
    }

    cvt_all_kernel<<<(unsigned)((CVT_UNITS + 255) / 256), 256>>>(
        (const float4*)w1, (const float4*)w2, (const float4*)w3, (const float4*)x, (float4*)out);
    scan_count_kernel<<<1, 256>>>(eidx);
    scatter_kernel<<<(A_TOTAL + 255) / 256, 256>>>(eidx, ew);

    gemm1_kernel<<<dim3(D_FF / BN, MAX_MTILES), 512, smem1>>>();
    gemm2_kernel<<<dim3(D_MODEL / BN, MAX_MTILES), 256, smem2>>>(out);
}

// round 12
// speedup vs baseline: 1.0602x; 1.0602x over previous
#include <cuda_runtime.h>
#include <cuda_fp16.h>
#include <cstdint>

#define N_EXPERTS 16
#define D_MODEL   1024
#define D_FF      2816
#define N_TOKENS  8192
#define TOP_K     2
#define A_TOTAL   (N_TOKENS * TOP_K)

#define BM 128
#define BK 64
#define BN 128

#define A_STH 72                   // A smem row stride (halves): 64 + 8 pad; ldmatrix conflict-free
#define B_STH 136                  // B smem row stride (halves): ldmatrix.trans conflict-free
#define A_STAGE_H (BM * A_STH)     // 9216 halves = 18432 B
#define B_STAGE_H (BK * B_STH)     // 8704 halves = 17408 B

#define MAX_SLOTS  (A_TOTAL + N_EXPERTS * BM)  // 18432
#define MAX_MTILES (MAX_SLOTS / BM)            // 144

// ---------------- scratch (device globals) ----------------
__device__ int    g_perm[MAX_SLOTS];
__device__ float  g_wgt[MAX_SLOTS];
__device__ int    g_offsets[N_EXPERTS];
__device__ int    g_tile_expert[MAX_MTILES];
__device__ __half g_Xh[(size_t)N_TOKENS * D_MODEL];            // fp16 x
__device__ __half g_Hh[(size_t)MAX_SLOTS * D_FF];              // fp16 SwiGLU activations
__device__ __half g_W1h[(size_t)N_EXPERTS * D_MODEL * D_FF];   // fp16 weights
__device__ __half g_W2h[(size_t)N_EXPERTS * D_MODEL * D_FF];
__device__ __half g_W3h[(size_t)N_EXPERTS * D_FF * D_MODEL];

// ---------------- helpers ----------------
__device__ __forceinline__ void mma16(float* c, const uint32_t* a, const uint32_t* b) {
    asm("mma.sync.aligned.m16n8k16.row.col.f32.f16.f16.f32 "
        "{%0,%1,%2,%3}, {%4,%5,%6,%7}, {%8,%9}, {%0,%1,%2,%3};\n"
        : "+f"(c[0]), "+f"(c[1]), "+f"(c[2]), "+f"(c[3])
        : "r"(a[0]), "r"(a[1]), "r"(a[2]), "r"(a[3]),
          "r"(b[0]), "r"(b[1]));
}
__device__ __forceinline__ void ldsm4(uint32_t* r, uint32_t addr) {
    asm volatile("ldmatrix.sync.aligned.m8n8.x4.shared.b16 {%0,%1,%2,%3}, [%4];"
                 : "=r"(r[0]), "=r"(r[1]), "=r"(r[2]), "=r"(r[3]) : "r"(addr));
}
__device__ __forceinline__ void ldsm4t(uint32_t* r, uint32_t addr) {
    asm volatile("ldmatrix.sync.aligned.m8n8.x4.trans.shared.b16 {%0,%1,%2,%3}, [%4];"
                 : "=r"(r[0]), "=r"(r[1]), "=r"(r[2]), "=r"(r[3]) : "r"(addr));
}
__device__ __forceinline__ float silu_f(float x) { return x / (1.0f + __expf(-x)); }
__device__ __forceinline__ uint32_t smem_u32(const void* p) {
    return (uint32_t)__cvta_generic_to_shared(p);
}
__device__ __forceinline__ void cp16(uint32_t dst, const void* src) {
    asm volatile("cp.async.cg.shared.global [%0], [%1], 16;" :: "r"(dst), "l"(src));
}
__device__ __forceinline__ void cp16_pred(uint32_t dst, const void* src, int valid) {
    int sz = valid ? 16 : 0;   // sz=0 zero-fills the 16B destination
    asm volatile("cp.async.cg.shared.global [%0], [%1], 16, %2;"
                 :: "r"(dst), "l"(src), "r"(sz));
}
#define CP_COMMIT() asm volatile("cp.async.commit_group;" ::: "memory")
#define CP_WAIT1()  asm volatile("cp.async.wait_group 1;"  ::: "memory")

// ---------------- launch 1: convert everything to fp16 + zero output ----------------
#define WU ((size_t)N_EXPERTS * D_MODEL * D_FF / 8)   // 5,767,168 units of 8 floats
#define XU ((size_t)N_TOKENS * D_MODEL / 8)           // 1,048,576
#define CVT_UNITS (3 * WU + 2 * XU)

__device__ __forceinline__ void cvt8(const float4* __restrict__ src, __half* __restrict__ dst, size_t u) {
    float4 a = src[2 * u], b = src[2 * u + 1];
    __half2 h[4];
    h[0] = __floats2half2_rn(a.x, a.y);
    h[1] = __floats2half2_rn(a.z, a.w);
    h[2] = __floats2half2_rn(b.x, b.y);
    h[3] = __floats2half2_rn(b.z, b.w);
    *(uint4*)(dst + 8 * u) = *(uint4*)h;
}

__global__ void cvt_all_kernel(const float4* __restrict__ w1, const float4* __restrict__ w2,
                               const float4* __restrict__ w3, const float4* __restrict__ x,
                               float4* __restrict__ out) {
    size_t i = (size_t)blockIdx.x * blockDim.x + threadIdx.x;
    if (i < WU)                cvt8(w1, g_W1h, i);
    else if (i < 2 * WU)       cvt8(w2, g_W2h, i - WU);
    else if (i < 3 * WU)       cvt8(w3, g_W3h, i - 2 * WU);
    else if (i < 3 * WU + XU)  cvt8(x,  g_Xh,  i - 3 * WU);
    else if (i < CVT_UNITS) {
        size_t u = i - 3 * WU - XU;
        out[2 * u]     = make_float4(0.f, 0.f, 0.f, 0.f);
        out[2 * u + 1] = make_float4(0.f, 0.f, 0.f, 0.f);
    }
}

// ---------------- launch 2: count + scan + perm init (single block) ----------------
__global__ void scan_count_kernel(const int* __restrict__ eidx) {
    __shared__ int hist[8][N_EXPERTS];
    const int tid = threadIdx.x;
    const int wid = tid >> 5;
    if (tid < 128) ((int*)hist)[tid] = 0;
    for (int i = tid; i < MAX_SLOTS; i += 256) g_perm[i] = -1;
    __syncthreads();
    const int4* e4 = (const int4*)eidx;
    for (int i = tid; i < A_TOTAL / 4; i += 256) {
        int4 e = e4[i];
        atomicAdd(&hist[wid][e.x], 1);
        atomicAdd(&hist[wid][e.y], 1);
        atomicAdd(&hist[wid][e.z], 1);
        atomicAdd(&hist[wid][e.w], 1);
    }
    __syncthreads();
    if (tid == 0) {
        for (int i = 0; i < MAX_MTILES; i++) g_tile_expert[i] = -1;
        int acc = 0;
        for (int e = 0; e < N_EXPERTS; e++) {
            int cnt = 0;
            for (int w = 0; w < 8; w++) cnt += hist[w][e];
            g_offsets[e] = acc;
            int nt = (cnt + BM - 1) / BM;
            int t0 = acc / BM;
            for (int i = 0; i < nt; i++) g_tile_expert[t0 + i] = e;
            acc += nt * BM;
        }
    }
}

// ---------------- launch 3: scatter ----------------
__global__ void scatter_kernel(const int* __restrict__ eidx,
                               const float* __restrict__ ew) {
    int i = blockIdx.x * blockDim.x + threadIdx.x;
    if (i < A_TOTAL) {
        int e = eidx[i];
        int p = atomicAdd(&g_offsets[e], 1);
        g_perm[p] = i / TOP_K;
        g_wgt[p]  = ew[i];
    }
}

// ---------------- launch 4: GEMM1: H = silu(X@W1) * (X@W2), fp16 MMA ----------------
// grid (D_FF/BN=22, 144), 512 thr (16 warps). Warps 4(m) x 4(n); warp tile 32x32.
// 2-stage pipeline with R10 schedule: wait, sync, compute, sync, issue.
__global__ void __launch_bounds__(512)
gemm1_kernel() {
    const int mt = blockIdx.y;
    const int e  = g_tile_expert[mt];
    if (e < 0) return;
    const int nb   = blockIdx.x * BN;
    const int row0 = mt * BM;

    extern __shared__ __half smem[];
    __half* sA  = smem;                       // 2 * A_STAGE_H
    __half* sB1 = sA  + 2 * A_STAGE_H;        // 2 * B_STAGE_H
    __half* sB2 = sB1 + 2 * B_STAGE_H;

    const int tid  = threadIdx.x;
    const int lane = tid & 31;
    const int wid  = tid >> 5;
    const int wm   = wid >> 2;      // 0..3
    const int wn   = wid & 3;       // 0..3
    const int m0   = wm * 32;
    const int nG   = wn * 32;
    const int g    = lane >> 2;
    const int t    = lane & 3;

    // A loader: 2 tasks. q0 = tid: m = tid>>3 (0..63), kq = tid&7; q1 = tid+512: m+64
    const int mA = tid >> 3, kqA = tid & 7;
    const int tok0 = g_perm[row0 + mA];
    const int tok1 = g_perm[row0 + mA + 64];
    const int av0 = (tok0 >= 0), av1 = (tok1 >= 0);
    const __half* apg0 = g_Xh + (size_t)(tok0 < 0 ? 0 : tok0) * D_MODEL + kqA * 8;
    const __half* apg1 = g_Xh + (size_t)(tok1 < 0 ? 0 : tok1) * D_MODEL + kqA * 8;
    const uint32_t dA0 = smem_u32(sA + mA * A_STH + kqA * 8);
    // second A task: constant smem offset +64 rows
    // B loaders: 2 tasks each. q0: k = tid>>4 (0..31), nq = tid&15; q1: k+32
    const int kB = tid >> 4, nqB = tid & 15;
    const __half* b1g = g_W1h + (size_t)e * D_MODEL * D_FF + (size_t)kB * D_FF + nb + nqB * 8;
    const __half* b2g = g_W2h + (size_t)e * D_MODEL * D_FF + (size_t)kB * D_FF + nb + nqB * 8;
    const uint32_t dB1 = smem_u32(sB1 + kB * B_STH + nqB * 8);
    const uint32_t dB2 = smem_u32(sB2 + kB * B_STH + nqB * 8);

    // ldmatrix lane offsets
    const int laR = (lane & 7) + 8 * ((lane >> 3) & 1);   // row within 16
    const int laK = 8 * (lane >> 4);                      // k-half select
    const uint32_t aoff  = smem_u32(sA)  + ((m0 + laR) * A_STH + laK) * 2;
    const uint32_t b1off = smem_u32(sB1) + (laR * B_STH + nG + laK) * 2;
    const uint32_t b2off = smem_u32(sB2) + (laR * B_STH + nG + laK) * 2;

    const int KT = D_MODEL / BK;   // 16

    auto issue = [&](int kt) {
        if (kt < KT) {
            const int s = kt & 1;
            const int kg = kt * BK;
            cp16_pred(dA0 + s * A_STAGE_H * 2,                 apg0 + kg, av0);
            cp16_pred(dA0 + s * A_STAGE_H * 2 + 64 * A_STH * 2, apg1 + kg, av1);
            cp16(dB1 + s * B_STAGE_H * 2,                  b1g + (size_t)kg * D_FF);
            cp16(dB1 + s * B_STAGE_H * 2 + 32 * B_STH * 2, b1g + (size_t)(kg + 32) * D_FF);
            cp16(dB2 + s * B_STAGE_H * 2,                  b2g + (size_t)kg * D_FF);
            cp16(dB2 + s * B_STAGE_H * 2 + 32 * B_STH * 2, b2g + (size_t)(kg + 32) * D_FF);
        }
        CP_COMMIT();
    };

    float accg[2][4][4] = {};
    float accv[2][4][4] = {};

    issue(0); issue(1);

    for (int kt = 0; kt < KT; kt++) {
        CP_WAIT1();
        __syncthreads();

        const int s = kt & 1;
        const uint32_t aS  = aoff  + s * A_STAGE_H * 2;
        const uint32_t b1S = b1off + s * B_STAGE_H * 2;
        const uint32_t b2S = b2off + s * B_STAGE_H * 2;

#pragma unroll
        for (int kf = 0; kf < 4; kf++) {
            uint32_t af[2][4];
            ldsm4(af[0], aS + kf * 32);
            ldsm4(af[1], aS + kf * 32 + 16 * A_STH * 2);
#pragma unroll
            for (int nj = 0; nj < 2; nj++) {
                uint32_t bb1[4], bb2[4];
                ldsm4t(bb1, b1S + kf * 16 * B_STH * 2 + nj * 32);
                ldsm4t(bb2, b2S + kf * 16 * B_STH * 2 + nj * 32);
#pragma unroll
                for (int mi = 0; mi < 2; mi++) {
                    mma16(accg[mi][2 * nj],     af[mi], bb1);
                    mma16(accg[mi][2 * nj + 1], af[mi], bb1 + 2);
                    mma16(accv[mi][2 * nj],     af[mi], bb2);
                    mma16(accv[mi][2 * nj + 1], af[mi], bb2 + 2);
                }
            }
        }
        __syncthreads();
        issue(kt + 2);
    }

    // epilogue: SwiGLU -> g_Hh (fp16)
#pragma unroll
    for (int mi = 0; mi < 2; mi++) {
        const int r = m0 + mi * 16 + g;
        const size_t h0 = (size_t)(row0 + r)     * D_FF;
        const size_t h8 = (size_t)(row0 + r + 8) * D_FF;
#pragma unroll
        for (int ni = 0; ni < 4; ni++) {
            const int c = nb + nG + ni * 8 + 2 * t;
            *(__half2*)&g_Hh[h0 + c] = __floats2half2_rn(
                silu_f(accg[mi][ni][0]) * accv[mi][ni][0],
                silu_f(accg[mi][ni][1]) * accv[mi][ni][1]);
            *(__half2*)&g_Hh[h8 + c] = __floats2half2_rn(
                silu_f(accg[mi][ni][2]) * accv[mi][ni][2],
                silu_f(accg[mi][ni][3]) * accv[mi][ni][3]);
        }
    }
}

// ---------------- launch 5: GEMM2: out += wgt * (H @ W3), fp16 MMA ----------------
// grid (D_MODEL/BN=8, 144), 256 thr, 2 CTAs/SM. Warps 2(m) x 4(n); warp tile 64x32.
// 2-stage pipeline with R10 schedule.
__global__ void __launch_bounds__(256, 2)
gemm2_kernel(float* __restrict__ out) {
    const int mt = blockIdx.y;
    const int e  = g_tile_expert[mt];
    if (e < 0) return;
    const int nb   = blockIdx.x * BN;
    const int row0 = mt * BM;

    extern __shared__ __half smem[];
    __half* sA = smem;                     // 2 * A_STAGE_H
    __half* sB = sA + 2 * A_STAGE_H;       // 2 * B_STAGE_H

    const int tid  = threadIdx.x;
    const int lane = tid & 31;
    const int wid  = tid >> 5;
    const int wm   = wid >> 2;      // 0..1
    const int wn   = wid & 3;       // 0..3
    const int m0   = wm * 64;
    const int nG   = wn * 32;
    const int g    = lane >> 2;
    const int t    = lane & 3;

    // A loader: 4 tasks. q = tid + 256j: m = q>>3 (0..127), kq = q&7
    const int mA = tid >> 3, kqA = tid & 7;
    const __half* apg = g_Hh + (size_t)(row0 + mA) * D_FF + kqA * 8;   // rows +32j
    const uint32_t dA = smem_u32(sA + mA * A_STH + kqA * 8);
    // B loader: 4 tasks. q: k = q>>4 (0..63), nq = q&15 -> k +16j
    const int kB = tid >> 4, nqB = tid & 15;
    const __half* bg = g_W3h + (size_t)e * D_FF * D_MODEL + (size_t)kB * D_MODEL + nb + nqB * 8;
    const uint32_t dB = smem_u32(sB + kB * B_STH + nqB * 8);

    const int laR = (lane & 7) + 8 * ((lane >> 3) & 1);
    const int laK = 8 * (lane >> 4);
    const uint32_t aoff = smem_u32(sA) + ((m0 + laR) * A_STH + laK) * 2;
    const uint32_t boff = smem_u32(sB) + (laR * B_STH + nG + laK) * 2;

    const int KT = D_FF / BK;   // 44

    auto issue = [&](int kt) {
        if (kt < KT) {
            const int s = kt & 1;
            const int kg = kt * BK;
#pragma unroll
            for (int j = 0; j < 4; j++)
                cp16(dA + s * A_STAGE_H * 2 + j * 32 * A_STH * 2,
                     apg + (size_t)(32 * j) * D_FF + kg);
#pragma unroll
            for (int j = 0; j < 4; j++)
                cp16(dB + s * B_STAGE_H * 2 + j * 16 * B_STH * 2,
                     bg + (size_t)(kg + 16 * j) * D_MODEL);
        }
        CP_COMMIT();
    };

    float acc[4][4][4] = {};

    issue(0); issue(1);

    for (int kt = 0; kt < KT; kt++) {
        CP_WAIT1();
        __syncthreads();

        const int s = kt & 1;
        const uint32_t aS = aoff + s * A_STAGE_H * 2;
        const uint32_t bS = boff + s * B_STAGE_H * 2;

#pragma unroll
        for (int kf = 0; kf < 4; kf++) {
            uint32_t af[4][4];
#pragma unroll
            for (int mi = 0; mi < 4; mi++)
                ldsm4(af[mi], aS + kf * 32 + mi * 16 * A_STH * 2);
#pragma unroll
            for (int nj = 0; nj < 2; nj++) {
                uint32_t bb[4];
                ldsm4t(bb, bS + kf * 16 * B_STH * 2 + nj * 32);
#pragma unroll
                for (int mi = 0; mi < 4; mi++) {
                    mma16(acc[mi][2 * nj],     af[mi], bb);
                    mma16(acc[mi][2 * nj + 1], af[mi], bb + 2);
                }
            }
        }
        __syncthreads();
        issue(kt + 2);
    }

    // epilogue: weighted scatter-add (exactly 2 commutative adds per token)
#pragma unroll
    for (int mi = 0; mi < 4; mi++) {
        const int r  = m0 + mi * 16 + g;
        const int s0 = row0 + r;
        const int s8 = s0 + 8;
        const int tk0 = g_perm[s0];
        const int tk8 = g_perm[s8];
        const float wt0 = (tk0 >= 0) ? g_wgt[s0] : 0.f;
        const float wt8 = (tk8 >= 0) ? g_wgt[s8] : 0.f;
#pragma unroll
        for (int ni = 0; ni < 4; ni++) {
            const int c = nb + nG + ni * 8 + 2 * t;
            if (tk0 >= 0) {
                atomicAdd(&out[(size_t)tk0 * D_MODEL + c    ], acc[mi][ni][0] * wt0);
                atomicAdd(&out[(size_t)tk0 * D_MODEL + c + 1], acc[mi][ni][1] * wt0);
            }
            if (tk8 >= 0) {
                atomicAdd(&out[(size_t)tk8 * D_MODEL + c    ], acc[mi][ni][2] * wt8);
                atomicAdd(&out[(size_t)tk8 * D_MODEL + c + 1], acc[mi][ni][3] * wt8);
            }
        }
    }
}

// ---------------- launch ----------------
extern "C" void kernel_launch(void* const* d_in, const int* in_sizes, int n_in,
                              void* d_out, int out_size) {
    const float* x    = (const float*)d_in[0];
    const int*   eidx = (const int*)  d_in[1];
    const float* ew   = (const float*)d_in[2];
    const float* w1   = (const float*)d_in[3];
    const float* w2   = (const float*)d_in[4];
    const float* w3   = (const float*)d_in[5];
    float* out = (float*)d_out;

    const int smem1 = 2 * (A_STAGE_H + 2 * B_STAGE_H) * 2;   // 106496 B -> 1 CTA/SM
    const int smem2 = 2 * (A_STAGE_H + B_STAGE_H) * 2;       //  71680 B -> 2 CTAs/SM
    static int attr_done = 0;
    if (!attr_done) {
        cudaFuncSetAttribute(gemm1_kernel, cudaFuncAttributeMaxDynamicSharedMemorySize, smem1);
        cudaFuncSetAttribute(gemm2_kernel, cudaFuncAttributeMaxDynamicSharedMemorySize, smem2);
        attr_done = 1;
    }

    cvt_all_kernel<<<(unsigned)((CVT_UNITS + 255) / 256), 256>>>(
        (const float4*)w1, (const float4*)w2, (const float4*)w3, (const float4*)x, (float4*)out);
    scan_count_kernel<<<1, 256>>>(eidx);
    scatter_kernel<<<(A_TOTAL + 255) / 256, 256>>>(eidx, ew);

    gemm1_kernel<<<dim3(D_FF / BN, MAX_MTILES), 512, smem1>>>();
    gemm2_kernel<<<dim3(D_MODEL / BN, MAX_MTILES), 256, smem2>>>(out);
}

// round 13
// speedup vs baseline: 1.0705x; 1.0097x over previous
#include <cuda_runtime.h>
#include <cuda_fp16.h>
#include <cstdint>

#define N_EXPERTS 16
#define D_MODEL   1024
#define D_FF      2816
#define N_TOKENS  8192
#define TOP_K     2
#define A_TOTAL   (N_TOKENS * TOP_K)

#define BM 128
#define BK 32
#define BN 128

#define A_STH 40                   // A smem row stride (halves): ldmatrix conflict-free
#define B_STH 136                  // B smem row stride (halves): ldmatrix.trans conflict-free
#define A_STAGE_H (BM * A_STH)     // 5120 halves = 10240 B
#define B_STAGE_H (BK * B_STH)     // 4352 halves =  8704 B

#define MAX_SLOTS  (A_TOTAL + N_EXPERTS * BM)  // 18432
#define MAX_MTILES (MAX_SLOTS / BM)            // 144
#define W3_CTAS_Y  16                          // extra grid rows in gemm1 for W3 cvt

// ---------------- scratch (device globals) ----------------
__device__ int    g_perm[MAX_SLOTS];
__device__ float  g_wgt[MAX_SLOTS];
__device__ int    g_offsets[N_EXPERTS];
__device__ int    g_tile_expert[MAX_MTILES];
__device__ __half g_Xh[(size_t)N_TOKENS * D_MODEL];            // fp16 x
__device__ __half g_Hh[(size_t)MAX_SLOTS * D_FF];              // fp16 SwiGLU activations
__device__ __half g_W1h[(size_t)N_EXPERTS * D_MODEL * D_FF];   // fp16 weights
__device__ __half g_W2h[(size_t)N_EXPERTS * D_MODEL * D_FF];
__device__ __half g_W3h[(size_t)N_EXPERTS * D_FF * D_MODEL];

// ---------------- helpers ----------------
__device__ __forceinline__ void mma16(float* c, const uint32_t* a, const uint32_t* b) {
    asm("mma.sync.aligned.m16n8k16.row.col.f32.f16.f16.f32 "
        "{%0,%1,%2,%3}, {%4,%5,%6,%7}, {%8,%9}, {%0,%1,%2,%3};\n"
        : "+f"(c[0]), "+f"(c[1]), "+f"(c[2]), "+f"(c[3])
        : "r"(a[0]), "r"(a[1]), "r"(a[2]), "r"(a[3]),
          "r"(b[0]), "r"(b[1]));
}
__device__ __forceinline__ void ldsm4(uint32_t* r, uint32_t addr) {
    asm volatile("ldmatrix.sync.aligned.m8n8.x4.shared.b16 {%0,%1,%2,%3}, [%4];"
                 : "=r"(r[0]), "=r"(r[1]), "=r"(r[2]), "=r"(r[3]) : "r"(addr));
}
__device__ __forceinline__ void ldsm4t(uint32_t* r, uint32_t addr) {
    asm volatile("ldmatrix.sync.aligned.m8n8.x4.trans.shared.b16 {%0,%1,%2,%3}, [%4];"
                 : "=r"(r[0]), "=r"(r[1]), "=r"(r[2]), "=r"(r[3]) : "r"(addr));
}
__device__ __forceinline__ float silu_f(float x) { return x / (1.0f + __expf(-x)); }
__device__ __forceinline__ uint32_t smem_u32(const void* p) {
    return (uint32_t)__cvta_generic_to_shared(p);
}
__device__ __forceinline__ void cp16(uint32_t dst, const void* src) {
    asm volatile("cp.async.cg.shared.global [%0], [%1], 16;" :: "r"(dst), "l"(src));
}
__device__ __forceinline__ void cp16_pred(uint32_t dst, const void* src, int valid) {
    int sz = valid ? 16 : 0;   // sz=0 zero-fills the 16B destination
    asm volatile("cp.async.cg.shared.global [%0], [%1], 16, %2;"
                 :: "r"(dst), "l"(src), "r"(sz));
}
#define CP_COMMIT() asm volatile("cp.async.commit_group;" ::: "memory")
#define CP_WAIT1()  asm volatile("cp.async.wait_group 1;"  ::: "memory")

// ---------------- conversion units ----------------
#define WU ((size_t)N_EXPERTS * D_MODEL * D_FF / 8)   // 5,767,168 units of 8 floats
#define XU ((size_t)N_TOKENS * D_MODEL / 8)           // 1,048,576
#define CVT_UNITS (2 * WU + 2 * XU)                   // W3 converted inside gemm1 grid
#define W3_UNITS_PER_CTA (WU / (22 * W3_CTAS_Y))      // 16384

__device__ __forceinline__ void cvt8(const float4* __restrict__ src, __half* __restrict__ dst, size_t u) {
    float4 a = src[2 * u], b = src[2 * u + 1];
    __half2 h[4];
    h[0] = __floats2half2_rn(a.x, a.y);
    h[1] = __floats2half2_rn(a.z, a.w);
    h[2] = __floats2half2_rn(b.x, b.y);
    h[3] = __floats2half2_rn(b.z, b.w);
    *(uint4*)(dst + 8 * u) = *(uint4*)h;
}

// ---------------- launch 1: convert W1, W2, x to fp16 + zero output ----------------
__global__ void cvt_all_kernel(const float4* __restrict__ w1, const float4* __restrict__ w2,
                               const float4* __restrict__ x, float4* __restrict__ out) {
    size_t i = (size_t)blockIdx.x * blockDim.x + threadIdx.x;
    if (i < WU)                cvt8(w1, g_W1h, i);
    else if (i < 2 * WU)       cvt8(w2, g_W2h, i - WU);
    else if (i < 2 * WU + XU)  cvt8(x,  g_Xh,  i - 2 * WU);
    else if (i < CVT_UNITS) {
        size_t u = i - 2 * WU - XU;
        out[2 * u]     = make_float4(0.f, 0.f, 0.f, 0.f);
        out[2 * u + 1] = make_float4(0.f, 0.f, 0.f, 0.f);
    }
}

// ---------------- launch 2: count + scan + perm init (single block) ----------------
__global__ void scan_count_kernel(const int* __restrict__ eidx) {
    __shared__ int hist[8][N_EXPERTS];
    const int tid = threadIdx.x;
    const int wid = tid >> 5;
    if (tid < 128) ((int*)hist)[tid] = 0;
    for (int i = tid; i < MAX_SLOTS; i += 256) g_perm[i] = -1;
    __syncthreads();
    const int4* e4 = (const int4*)eidx;
    for (int i = tid; i < A_TOTAL / 4; i += 256) {
        int4 e = e4[i];
        atomicAdd(&hist[wid][e.x], 1);
        atomicAdd(&hist[wid][e.y], 1);
        atomicAdd(&hist[wid][e.z], 1);
        atomicAdd(&hist[wid][e.w], 1);
    }
    __syncthreads();
    if (tid == 0) {
        for (int i = 0; i < MAX_MTILES; i++) g_tile_expert[i] = -1;
        int acc = 0;
        for (int e = 0; e < N_EXPERTS; e++) {
            int cnt = 0;
            for (int w = 0; w < 8; w++) cnt += hist[w][e];
            g_offsets[e] = acc;
            int nt = (cnt + BM - 1) / BM;
            int t0 = acc / BM;
            for (int i = 0; i < nt; i++) g_tile_expert[t0 + i] = e;
            acc += nt * BM;
        }
    }
}

// ---------------- launch 3: scatter ----------------
__global__ void scatter_kernel(const int* __restrict__ eidx,
                               const float* __restrict__ ew) {
    int i = blockIdx.x * blockDim.x + threadIdx.x;
    if (i < A_TOTAL) {
        int e = eidx[i];
        int p = atomicAdd(&g_offsets[e], 1);
        g_perm[p] = i / TOP_K;
        g_wgt[p]  = ew[i];
    }
}

// ---------------- launch 4: GEMM1: H = silu(X@W1) * (X@W2), fp16 MMA ----------------
// grid (22, 144 + 16), 512 thr. y<144: GEMM (warps 4x4, warp tile 32x32, 3-stage,
// ONE barrier per kt, issue AFTER compute). y>=144: W3 fp32->fp16 conversion.
__global__ void __launch_bounds__(512)
gemm1_kernel(const float* __restrict__ w3src) {
    const int mt = blockIdx.y;
    if (mt >= MAX_MTILES) {
        // W3 conversion role: 22*16 CTAs x 16384 units
        size_t base = ((size_t)(mt - MAX_MTILES) * 22 + blockIdx.x) * W3_UNITS_PER_CTA;
        const float4* src = (const float4*)w3src;
        for (int j = threadIdx.x; j < (int)W3_UNITS_PER_CTA; j += 512)
            cvt8(src, g_W3h, base + j);
        return;
    }
    const int e = g_tile_expert[mt];
    if (e < 0) return;
    const int nb   = blockIdx.x * BN;
    const int row0 = mt * BM;

    extern __shared__ __half smem[];
    __half* sA  = smem;                       // 3 * A_STAGE_H
    __half* sB1 = sA  + 3 * A_STAGE_H;        // 3 * B_STAGE_H
    __half* sB2 = sB1 + 3 * B_STAGE_H;

    const int tid  = threadIdx.x;
    const int lane = tid & 31;
    const int wid  = tid >> 5;
    const int wm   = wid >> 2;      // 0..3
    const int wn   = wid & 3;       // 0..3
    const int m0   = wm * 32;
    const int nG   = wn * 32;
    const int g    = lane >> 2;
    const int t    = lane & 3;

    // A cp.async loader: 1 task/thread: m = tid>>2 (0..127), 16B quad kq = tid&3
    const int mA = tid >> 2, kqA = tid & 3;
    const int tok = g_perm[row0 + mA];
    const int av  = (tok >= 0);
    const __half* apg = g_Xh + (size_t)(tok < 0 ? 0 : tok) * D_MODEL + kqA * 8;
    const uint32_t dA = smem_u32(sA + mA * A_STH + kqA * 8);
    // B loaders: 1 task/thread each: k = tid>>4 (0..31), 16B quad nq = tid&15
    const int kB = tid >> 4, nqB = tid & 15;
    const __half* b1g = g_W1h + (size_t)e * D_MODEL * D_FF + (size_t)kB * D_FF + nb + nqB * 8;
    const __half* b2g = g_W2h + (size_t)e * D_MODEL * D_FF + (size_t)kB * D_FF + nb + nqB * 8;
    const uint32_t dB1 = smem_u32(sB1 + kB * B_STH + nqB * 8);
    const uint32_t dB2 = smem_u32(sB2 + kB * B_STH + nqB * 8);

    // ldmatrix lane offsets
    const int laR = (lane & 7) + 8 * ((lane >> 3) & 1);   // row within 16
    const int laK = 8 * (lane >> 4);                      // k-half select
    const uint32_t aoff  = smem_u32(sA)  + ((m0 + laR) * A_STH + laK) * 2;
    const uint32_t b1off = smem_u32(sB1) + (laR * B_STH + nG + laK) * 2;
    const uint32_t b2off = smem_u32(sB2) + (laR * B_STH + nG + laK) * 2;

    const int KT = D_MODEL / BK;   // 32

    auto issue = [&](int kt, int st) {
        if (kt < KT) {
            const int kg = kt * BK;
            cp16_pred(dA + st * A_STAGE_H * 2, apg + kg, av);
            cp16(dB1 + st * B_STAGE_H * 2, b1g + (size_t)kg * D_FF);
            cp16(dB2 + st * B_STAGE_H * 2, b2g + (size_t)kg * D_FF);
        }
        CP_COMMIT();
    };

    float accg[2][4][4] = {};
    float accv[2][4][4] = {};

    issue(0, 0); issue(1, 1);

    int s = 0, s2 = 2;   // s: compute stage; s2: fill target = (kt-1)%3, safe post-sync
    for (int kt = 0; kt < KT; kt++) {
        CP_WAIT1();
        __syncthreads();

        const uint32_t aS  = aoff  + s * A_STAGE_H * 2;
        const uint32_t b1S = b1off + s * B_STAGE_H * 2;
        const uint32_t b2S = b2off + s * B_STAGE_H * 2;

#pragma unroll
        for (int kf = 0; kf < 2; kf++) {
            uint32_t af[2][4];
            ldsm4(af[0], aS + kf * 32);
            ldsm4(af[1], aS + kf * 32 + 16 * A_STH * 2);
#pragma unroll
            for (int nj = 0; nj < 2; nj++) {
                uint32_t bb1[4], bb2[4];
                ldsm4t(bb1, b1S + kf * 16 * B_STH * 2 + nj * 32);
                ldsm4t(bb2, b2S + kf * 16 * B_STH * 2 + nj * 32);
#pragma unroll
                for (int mi = 0; mi < 2; mi++) {
                    mma16(accg[mi][2 * nj],     af[mi], bb1);
                    mma16(accg[mi][2 * nj + 1], af[mi], bb1 + 2);
                    mma16(accv[mi][2 * nj],     af[mi], bb2);
                    mma16(accv[mi][2 * nj + 1], af[mi], bb2 + 2);
                }
            }
        }
        issue(kt + 2, s2);   // after compute; target stage finished by all pre-sync
        if (++s == 3) s = 0;
        if (++s2 == 3) s2 = 0;
    }

    // epilogue: SwiGLU -> g_Hh (fp16)
#pragma unroll
    for (int mi = 0; mi < 2; mi++) {
        const int r = m0 + mi * 16 + g;
        const size_t h0 = (size_t)(row0 + r)     * D_FF;
        const size_t h8 = (size_t)(row0 + r + 8) * D_FF;
#pragma unroll
        for (int ni = 0; ni < 4; ni++) {
            const int c = nb + nG + ni * 8 + 2 * t;
            *(__half2*)&g_Hh[h0 + c] = __floats2half2_rn(
                silu_f(accg[mi][ni][0]) * accv[mi][ni][0],
                silu_f(accg[mi][ni][1]) * accv[mi][ni][1]);
            *(__half2*)&g_Hh[h8 + c] = __floats2half2_rn(
                silu_f(accg[mi][ni][2]) * accv[mi][ni][2],
                silu_f(accg[mi][ni][3]) * accv[mi][ni][3]);
        }
    }
}

// ---------------- launch 5: GEMM2: out += wgt * (H @ W3), fp16 MMA ----------------
// grid (8, 144), 256 thr, 2 CTAs/SM. Warps 2(m) x 4(n); warp tile 64x32.
// 3-stage, ONE barrier per kt, issue AFTER compute.
__global__ void __launch_bounds__(256, 2)
gemm2_kernel(float* __restrict__ out) {
    const int mt = blockIdx.y;
    const int e  = g_tile_expert[mt];
    if (e < 0) return;
    const int nb   = blockIdx.x * BN;
    const int row0 = mt * BM;

    extern __shared__ __half smem[];
    __half* sA = smem;                     // 3 * A_STAGE_H
    __half* sB = sA + 3 * A_STAGE_H;       // 3 * B_STAGE_H

    const int tid  = threadIdx.x;
    const int lane = tid & 31;
    const int wid  = tid >> 5;
    const int wm   = wid >> 2;      // 0..1
    const int wn   = wid & 3;       // 0..3
    const int m0   = wm * 64;
    const int nG   = wn * 32;
    const int g    = lane >> 2;
    const int t    = lane & 3;

    // A loader: 2 tasks: q = tid + 256j: m = q>>2, kq = q&3
    const __half* apg[2];
    uint32_t dA[2];
#pragma unroll
    for (int j = 0; j < 2; j++) {
        const int q = tid + 256 * j;
        const int m = q >> 2, kq = q & 3;
        apg[j] = g_Hh + (size_t)(row0 + m) * D_FF + kq * 8;
        dA[j]  = smem_u32(sA + m * A_STH + kq * 8);
    }
    // B loader: 2 tasks: q: k = q>>4, nq = q&15
    const __half* bg[2];
    uint32_t dB[2];
#pragma unroll
    for (int j = 0; j < 2; j++) {
        const int q = tid + 256 * j;
        const int k = q >> 4, nq = q & 15;
        bg[j] = g_W3h + (size_t)e * D_FF * D_MODEL + (size_t)k * D_MODEL + nb + nq * 8;
        dB[j] = smem_u32(sB + k * B_STH + nq * 8);
    }

    const int laR = (lane & 7) + 8 * ((lane >> 3) & 1);
    const int laK = 8 * (lane >> 4);
    const uint32_t aoff = smem_u32(sA) + ((m0 + laR) * A_STH + laK) * 2;
    const uint32_t boff = smem_u32(sB) + (laR * B_STH + nG + laK) * 2;

    const int KT = D_FF / BK;   // 88

    auto issue = [&](int kt, int st) {
        if (kt < KT) {
            const int kg = kt * BK;
#pragma unroll
            for (int j = 0; j < 2; j++) cp16(dA[j] + st * A_STAGE_H * 2, apg[j] + kg);
#pragma unroll
            for (int j = 0; j < 2; j++) cp16(dB[j] + st * B_STAGE_H * 2, bg[j] + (size_t)kg * D_MODEL);
        }
        CP_COMMIT();
    };

    float acc[4][4][4] = {};

    issue(0, 0); issue(1, 1);

    int s = 0, s2 = 2;
    for (int kt = 0; kt < KT; kt++) {
        CP_WAIT1();
        __syncthreads();

        const uint32_t aS = aoff + s * A_STAGE_H * 2;
        const uint32_t bS = boff + s * B_STAGE_H * 2;

#pragma unroll
        for (int kf = 0; kf < 2; kf++) {
            uint32_t af[4][4];
#pragma unroll
            for (int mi = 0; mi < 4; mi++)
                ldsm4(af[mi], aS + kf * 32 + mi * 16 * A_STH * 2);
#pragma unroll
            for (int nj = 0; nj < 2; nj++) {
                uint32_t bb[4];
                ldsm4t(bb, bS + kf * 16 * B_STH * 2 + nj * 32);
#pragma unroll
                for (int mi = 0; mi < 4; mi++) {
                    mma16(acc[mi][2 * nj],     af[mi], bb);
                    mma16(acc[mi][2 * nj + 1], af[mi], bb + 2);
                }
            }
        }
        issue(kt + 2, s2);
        if (++s == 3) s = 0;
        if (++s2 == 3) s2 = 0;
    }

    // epilogue: weighted scatter-add (exactly 2 commutative adds per token)
#pragma unroll
    for (int mi = 0; mi < 4; mi++) {
        const int r  = m0 + mi * 16 + g;
        const int s0 = row0 + r;
        const int s8 = s0 + 8;
        const int tk0 = g_perm[s0];
        const int tk8 = g_perm[s8];
        const float wt0 = (tk0 >= 0) ? g_wgt[s0] : 0.f;
        const float wt8 = (tk8 >= 0) ? g_wgt[s8] : 0.f;
#pragma unroll
        for (int ni = 0; ni < 4; ni++) {
            const int c = nb + nG + ni * 8 + 2 * t;
            if (tk0 >= 0) {
                atomicAdd(&out[(size_t)tk0 * D_MODEL + c    ], acc[mi][ni][0] * wt0);
                atomicAdd(&out[(size_t)tk0 * D_MODEL + c + 1], acc[mi][ni][1] * wt0);
            }
            if (tk8 >= 0) {
                atomicAdd(&out[(size_t)tk8 * D_MODEL + c    ], acc[mi][ni][2] * wt8);
                atomicAdd(&out[(size_t)tk8 * D_MODEL + c + 1], acc[mi][ni][3] * wt8);
            }
        }
    }
}

// ---------------- launch ----------------
extern "C" void kernel_launch(void* const* d_in, const int* in_sizes, int n_in,
                              void* d_out, int out_size) {
    const float* x    = (const float*)d_in[0];
    const int*   eidx = (const int*)  d_in[1];
    const float* ew   = (const float*)d_in[2];
    const float* w1   = (const float*)d_in[3];
    const float* w2   = (const float*)d_in[4];
    const float* w3   = (const float*)d_in[5];
    float* out = (float*)d_out;

    const int smem1 = 3 * (A_STAGE_H + 2 * B_STAGE_H) * 2;   // 82944 B -> 1 CTA/SM
    const int smem2 = 3 * (A_STAGE_H + B_STAGE_H) * 2;       // 56832 B -> 2 CTAs/SM
    static int attr_done = 0;
    if (!attr_done) {
        cudaFuncSetAttribute(gemm1_kernel, cudaFuncAttributeMaxDynamicSharedMemorySize, smem1);
        cudaFuncSetAttribute(gemm2_kernel, cudaFuncAttributeMaxDynamicSharedMemorySize, smem2);
        attr_done = 1;
    }

    cvt_all_kernel<<<(unsigned)((CVT_UNITS + 255) / 256), 256>>>(
        (const float4*)w1, (const float4*)w2, (const float4*)x, (float4*)out);
    scan_count_kernel<<<1, 256>>>(eidx);
    scatter_kernel<<<(A_TOTAL + 255) / 256, 256>>>(eidx, ew);

    gemm1_kernel<<<dim3(D_FF / BN, MAX_MTILES + W3_CTAS_Y), 512, smem1>>>(w3);
    gemm2_kernel<<<dim3(D_MODEL / BN, MAX_MTILES), 256, smem2>>>(out);
}

// round 14
// speedup vs baseline: 1.1737x; 1.0964x over previous
#include <cuda_runtime.h>
#include <cuda_fp16.h>
#include <cstdint>

#define N_EXPERTS 16
#define D_MODEL   1024
#define D_FF      2816
#define N_TOKENS  8192
#define TOP_K     2
#define A_TOTAL   (N_TOKENS * TOP_K)

#define BM 128
#define BK 32
#define BN 128

#define A_STH 40                   // A smem row stride (halves): ldmatrix conflict-free
#define B_STH 136                  // B smem row stride (halves): ldmatrix.trans conflict-free
#define A_STAGE_H (BM * A_STH)     // 5120 halves = 10240 B
#define B_STAGE_H (BK * B_STH)     // 4352 halves =  8704 B

#define MAX_SLOTS  (A_TOTAL + N_EXPERTS * BM)  // 18432
#define MAX_MTILES (MAX_SLOTS / BM)            // 144

// ---------------- scratch (device globals) ----------------
__device__ int    g_perm[MAX_SLOTS];
__device__ float  g_wgt[MAX_SLOTS];
__device__ int    g_tile_expert[MAX_MTILES];
__device__ __half g_Xh[(size_t)N_TOKENS * D_MODEL];            // fp16 x
__device__ __half g_Hh[(size_t)MAX_SLOTS * D_FF];              // fp16 SwiGLU activations
__device__ __half g_W1h[(size_t)N_EXPERTS * D_MODEL * D_FF];   // fp16 weights
__device__ __half g_W2h[(size_t)N_EXPERTS * D_MODEL * D_FF];
__device__ __half g_W3h[(size_t)N_EXPERTS * D_FF * D_MODEL];

// ---------------- helpers ----------------
__device__ __forceinline__ void mma16(float* c, const uint32_t* a, const uint32_t* b) {
    asm("mma.sync.aligned.m16n8k16.row.col.f32.f16.f16.f32 "
        "{%0,%1,%2,%3}, {%4,%5,%6,%7}, {%8,%9}, {%0,%1,%2,%3};\n"
        : "+f"(c[0]), "+f"(c[1]), "+f"(c[2]), "+f"(c[3])
        : "r"(a[0]), "r"(a[1]), "r"(a[2]), "r"(a[3]),
          "r"(b[0]), "r"(b[1]));
}
__device__ __forceinline__ void ldsm4(uint32_t* r, uint32_t addr) {
    asm volatile("ldmatrix.sync.aligned.m8n8.x4.shared.b16 {%0,%1,%2,%3}, [%4];"
                 : "=r"(r[0]), "=r"(r[1]), "=r"(r[2]), "=r"(r[3]) : "r"(addr));
}
__device__ __forceinline__ void ldsm4t(uint32_t* r, uint32_t addr) {
    asm volatile("ldmatrix.sync.aligned.m8n8.x4.trans.shared.b16 {%0,%1,%2,%3}, [%4];"
                 : "=r"(r[0]), "=r"(r[1]), "=r"(r[2]), "=r"(r[3]) : "r"(addr));
}
__device__ __forceinline__ float silu_f(float x) { return x / (1.0f + __expf(-x)); }
__device__ __forceinline__ uint32_t smem_u32(const void* p) {
    return (uint32_t)__cvta_generic_to_shared(p);
}
__device__ __forceinline__ void cp16(uint32_t dst, const void* src) {
    asm volatile("cp.async.cg.shared.global [%0], [%1], 16;" :: "r"(dst), "l"(src));
}
__device__ __forceinline__ void cp16_pred(uint32_t dst, const void* src, int valid) {
    int sz = valid ? 16 : 0;   // sz=0 zero-fills the 16B destination
    asm volatile("cp.async.cg.shared.global [%0], [%1], 16, %2;"
                 :: "r"(dst), "l"(src), "r"(sz));
}
#define CP_COMMIT() asm volatile("cp.async.commit_group;" ::: "memory")
#define CP_WAIT1()  asm volatile("cp.async.wait_group 1;"  ::: "memory")

// ---------------- launch 1: convert everything to fp16 + zero output ----------------
#define WU ((size_t)N_EXPERTS * D_MODEL * D_FF / 8)   // 5,767,168 units of 8 floats
#define XU ((size_t)N_TOKENS * D_MODEL / 8)           // 1,048,576
#define CVT_UNITS (3 * WU + 2 * XU)

__device__ __forceinline__ void cvt8(const float4* __restrict__ src, __half* __restrict__ dst, size_t u) {
    float4 a = src[2 * u], b = src[2 * u + 1];
    __half2 h[4];
    h[0] = __floats2half2_rn(a.x, a.y);
    h[1] = __floats2half2_rn(a.z, a.w);
    h[2] = __floats2half2_rn(b.x, b.y);
    h[3] = __floats2half2_rn(b.z, b.w);
    *(uint4*)(dst + 8 * u) = *(uint4*)h;
}

__global__ void cvt_all_kernel(const float4* __restrict__ w1, const float4* __restrict__ w2,
                               const float4* __restrict__ w3, const float4* __restrict__ x,
                               float4* __restrict__ out) {
    size_t i = (size_t)blockIdx.x * blockDim.x + threadIdx.x;
    if (i < WU)                cvt8(w1, g_W1h, i);
    else if (i < 2 * WU)       cvt8(w2, g_W2h, i - WU);
    else if (i < 3 * WU)       cvt8(w3, g_W3h, i - 2 * WU);
    else if (i < 3 * WU + XU)  cvt8(x,  g_Xh,  i - 3 * WU);
    else if (i < CVT_UNITS) {
        size_t u = i - 3 * WU - XU;
        out[2 * u]     = make_float4(0.f, 0.f, 0.f, 0.f);
        out[2 * u + 1] = make_float4(0.f, 0.f, 0.f, 0.f);
    }
}

// ---------------- launch 2: count + scan + scatter (single block) ----------------
__global__ void scan_scatter_kernel(const int* __restrict__ eidx,
                                    const float* __restrict__ ew) {
    __shared__ int hist[8][N_EXPERTS];
    __shared__ int soff[N_EXPERTS];
    const int tid = threadIdx.x;
    const int wid = tid >> 5;
    if (tid < 128) ((int*)hist)[tid] = 0;
    for (int i = tid; i < MAX_SLOTS; i += 256) g_perm[i] = -1;
    __syncthreads();
    const int4* e4 = (const int4*)eidx;
    for (int i = tid; i < A_TOTAL / 4; i += 256) {
        int4 e = e4[i];
        atomicAdd(&hist[wid][e.x], 1);
        atomicAdd(&hist[wid][e.y], 1);
        atomicAdd(&hist[wid][e.z], 1);
        atomicAdd(&hist[wid][e.w], 1);
    }
    __syncthreads();
    if (tid == 0) {
        for (int i = 0; i < MAX_MTILES; i++) g_tile_expert[i] = -1;
        int acc = 0;
        for (int e = 0; e < N_EXPERTS; e++) {
            int cnt = 0;
            for (int w = 0; w < 8; w++) cnt += hist[w][e];
            soff[e] = acc;
            int nt = (cnt + BM - 1) / BM;
            int t0 = acc / BM;
            for (int i = 0; i < nt; i++) g_tile_expert[t0 + i] = e;
            acc += nt * BM;
        }
    }
    __syncthreads();
    for (int i = tid; i < A_TOTAL; i += 256) {
        int e = eidx[i];
        int p = atomicAdd(&soff[e], 1);
        g_perm[p] = i / TOP_K;
        g_wgt[p]  = ew[i];
    }
}

// ---------------- launch 3: GEMM1: H = silu(X@W1) * (X@W2), fp16 MMA ----------------
// grid (D_FF/BN=22, 144), 512 thr (16 warps). Warps 4(m) x 4(n); warp tile 32x32.
__global__ void __launch_bounds__(512)
gemm1_kernel() {
    const int mt = blockIdx.y;
    const int e  = g_tile_expert[mt];
    if (e < 0) return;
    const int nb   = blockIdx.x * BN;
    const int row0 = mt * BM;

    extern __shared__ __half smem[];
    __half* sA  = smem;                       // 2 * A_STAGE_H
    __half* sB1 = sA  + 2 * A_STAGE_H;        // 2 * B_STAGE_H
    __half* sB2 = sB1 + 2 * B_STAGE_H;

    const int tid  = threadIdx.x;
    const int lane = tid & 31;
    const int wid  = tid >> 5;
    const int wm   = wid >> 2;      // 0..3
    const int wn   = wid & 3;       // 0..3
    const int m0   = wm * 32;
    const int nG   = wn * 32;
    const int g    = lane >> 2;
    const int t    = lane & 3;

    // A cp.async loader: 1 task/thread: m = tid>>2 (0..127), 16B quad kq = tid&3
    const int mA = tid >> 2, kqA = tid & 3;
    const int tok = g_perm[row0 + mA];
    const int av  = (tok >= 0);
    const __half* apg = g_Xh + (size_t)(tok < 0 ? 0 : tok) * D_MODEL + kqA * 8;
    const uint32_t dA = smem_u32(sA + mA * A_STH + kqA * 8);
    // B loaders: 1 task/thread each: k = tid>>4 (0..31), 16B quad nq = tid&15
    const int kB = tid >> 4, nqB = tid & 15;
    const __half* b1g = g_W1h + (size_t)e * D_MODEL * D_FF + (size_t)kB * D_FF + nb + nqB * 8;
    const __half* b2g = g_W2h + (size_t)e * D_MODEL * D_FF + (size_t)kB * D_FF + nb + nqB * 8;
    const uint32_t dB1 = smem_u32(sB1 + kB * B_STH + nqB * 8);
    const uint32_t dB2 = smem_u32(sB2 + kB * B_STH + nqB * 8);

    // ldmatrix lane offsets
    const int laR = (lane & 7) + 8 * ((lane >> 3) & 1);   // row within 16
    const int laK = 8 * (lane >> 4);                      // k-half select
    const uint32_t aoff  = smem_u32(sA)  + ((m0 + laR) * A_STH + laK) * 2;
    const uint32_t b1off = smem_u32(sB1) + (laR * B_STH + nG + laK) * 2;
    const uint32_t b2off = smem_u32(sB2) + (laR * B_STH + nG + laK) * 2;

    const int KT = D_MODEL / BK;   // 32

    auto issue = [&](int kt) {
        if (kt < KT) {
            const int s = kt & 1;
            const int kg = kt * BK;
            cp16_pred(dA + s * A_STAGE_H * 2, apg + kg, av);
            cp16(dB1 + s * B_STAGE_H * 2, b1g + (size_t)kg * D_FF);
            cp16(dB2 + s * B_STAGE_H * 2, b2g + (size_t)kg * D_FF);
        }
        CP_COMMIT();
    };

    float accg[2][4][4] = {};
    float accv[2][4][4] = {};

    issue(0); issue(1);

    for (int kt = 0; kt < KT; kt++) {
        CP_WAIT1();
        __syncthreads();

        const int s = kt & 1;
        const uint32_t aS  = aoff  + s * A_STAGE_H * 2;
        const uint32_t b1S = b1off + s * B_STAGE_H * 2;
        const uint32_t b2S = b2off + s * B_STAGE_H * 2;

#pragma unroll
        for (int kf = 0; kf < 2; kf++) {
            uint32_t af[2][4];
            ldsm4(af[0], aS + kf * 32);
            ldsm4(af[1], aS + kf * 32 + 16 * A_STH * 2);
#pragma unroll
            for (int nj = 0; nj < 2; nj++) {
                uint32_t bb1[4], bb2[4];
                ldsm4t(bb1, b1S + kf * 16 * B_STH * 2 + nj * 32);
                ldsm4t(bb2, b2S + kf * 16 * B_STH * 2 + nj * 32);
#pragma unroll
                for (int mi = 0; mi < 2; mi++) {
                    mma16(accg[mi][2 * nj],     af[mi], bb1);
                    mma16(accg[mi][2 * nj + 1], af[mi], bb1 + 2);
                    mma16(accv[mi][2 * nj],     af[mi], bb2);
                    mma16(accv[mi][2 * nj + 1], af[mi], bb2 + 2);
                }
            }
        }
        __syncthreads();
        issue(kt + 2);
    }

    // epilogue: SwiGLU -> g_Hh (fp16)
#pragma unroll
    for (int mi = 0; mi < 2; mi++) {
        const int r = m0 + mi * 16 + g;
        const size_t h0 = (size_t)(row0 + r)     * D_FF;
        const size_t h8 = (size_t)(row0 + r + 8) * D_FF;
#pragma unroll
        for (int ni = 0; ni < 4; ni++) {
            const int c = nb + nG + ni * 8 + 2 * t;
            *(__half2*)&g_Hh[h0 + c] = __floats2half2_rn(
                silu_f(accg[mi][ni][0]) * accv[mi][ni][0],
                silu_f(accg[mi][ni][1]) * accv[mi][ni][1]);
            *(__half2*)&g_Hh[h8 + c] = __floats2half2_rn(
                silu_f(accg[mi][ni][2]) * accv[mi][ni][2],
                silu_f(accg[mi][ni][3]) * accv[mi][ni][3]);
        }
    }
}

// ---------------- launch 4: GEMM2: out += wgt * (H @ W3), fp16 MMA ----------------
// grid (D_MODEL/BN=8, 144), 256 thr, 2 CTAs/SM. Warps 2(m) x 4(n); warp tile 64x32.
__global__ void __launch_bounds__(256, 2)
gemm2_kernel(float* __restrict__ out) {
    const int mt = blockIdx.y;
    const int e  = g_tile_expert[mt];
    if (e < 0) return;
    const int nb   = blockIdx.x * BN;
    const int row0 = mt * BM;

    extern __shared__ __half smem[];
    __half* sA = smem;                     // 2 * A_STAGE_H
    __half* sB = sA + 2 * A_STAGE_H;       // 2 * B_STAGE_H

    const int tid  = threadIdx.x;
    const int lane = tid & 31;
    const int wid  = tid >> 5;
    const int wm   = wid >> 2;      // 0..1
    const int wn   = wid & 3;       // 0..3
    const int m0   = wm * 64;
    const int nG   = wn * 32;
    const int g    = lane >> 2;
    const int t    = lane & 3;

    // A loader: 2 tasks: q = tid + 256j: m = q>>2, kq = q&3
    const __half* apg[2];
    uint32_t dA[2];
#pragma unroll
    for (int j = 0; j < 2; j++) {
        const int q = tid + 256 * j;
        const int m = q >> 2, kq = q & 3;
        apg[j] = g_Hh + (size_t)(row0 + m) * D_FF + kq * 8;
        dA[j]  = smem_u32(sA + m * A_STH + kq * 8);
    }
    // B loader: 2 tasks: q: k = q>>4, nq = q&15
    const __half* bg[2];
    uint32_t dB[2];
#pragma unroll
    for (int j = 0; j < 2; j++) {
        const int q = tid + 256 * j;
        const int k = q >> 4, nq = q & 15;
        bg[j] = g_W3h + (size_t)e * D_FF * D_MODEL + (size_t)k * D_MODEL + nb + nq * 8;
        dB[j] = smem_u32(sB + k * B_STH + nq * 8);
    }

    const int laR = (lane & 7) + 8 * ((lane >> 3) & 1);
    const int laK = 8 * (lane >> 4);
    const uint32_t aoff = smem_u32(sA) + ((m0 + laR) * A_STH + laK) * 2;
    const uint32_t boff = smem_u32(sB) + (laR * B_STH + nG + laK) * 2;

    const int KT = D_FF / BK;   // 88

    auto issue = [&](int kt) {
        if (kt < KT) {
            const int s = kt & 1;
            const int kg = kt * BK;
#pragma unroll
            for (int j = 0; j < 2; j++) cp16(dA[j] + s * A_STAGE_H * 2, apg[j] + kg);
#pragma unroll
            for (int j = 0; j < 2; j++) cp16(dB[j] + s * B_STAGE_H * 2, bg[j] + (size_t)kg * D_MODEL);
        }
        CP_COMMIT();
    };

    float acc[4][4][4] = {};

    issue(0); issue(1);

    for (int kt = 0; kt < KT; kt++) {
        CP_WAIT1();
        __syncthreads();

        const int s = kt & 1;
        const uint32_t aS = aoff + s * A_STAGE_H * 2;
        const uint32_t bS = boff + s * B_STAGE_H * 2;

#pragma unroll
        for (int kf = 0; kf < 2; kf++) {
            uint32_t af[4][4];
#pragma unroll
            for (int mi = 0; mi < 4; mi++)
                ldsm4(af[mi], aS + kf * 32 + mi * 16 * A_STH * 2);
#pragma unroll
            for (int nj = 0; nj < 2; nj++) {
                uint32_t bb[4];
                ldsm4t(bb, bS + kf * 16 * B_STH * 2 + nj * 32);
#pragma unroll
                for (int mi = 0; mi < 4; mi++) {
                    mma16(acc[mi][2 * nj],     af[mi], bb);
                    mma16(acc[mi][2 * nj + 1], af[mi], bb + 2);
                }
            }
        }
        __syncthreads();
        issue(kt + 2);
    }

    // epilogue: weighted scatter-add (exactly 2 commutative adds per token)
#pragma unroll
    for (int mi = 0; mi < 4; mi++) {
        const int r  = m0 + mi * 16 + g;
        const int s0 = row0 + r;
        const int s8 = s0 + 8;
        const int tk0 = g_perm[s0];
        const int tk8 = g_perm[s8];
        const float wt0 = (tk0 >= 0) ? g_wgt[s0] : 0.f;
        const float wt8 = (tk8 >= 0) ? g_wgt[s8] : 0.f;
#pragma unroll
        for (int ni = 0; ni < 4; ni++) {
            const int c = nb + nG + ni * 8 + 2 * t;
            if (tk0 >= 0) {
                atomicAdd(&out[(size_t)tk0 * D_MODEL + c    ], acc[mi][ni][0] * wt0);
                atomicAdd(&out[(size_t)tk0 * D_MODEL + c + 1], acc[mi][ni][1] * wt0);
            }
            if (tk8 >= 0) {
                atomicAdd(&out[(size_t)tk8 * D_MODEL + c    ], acc[mi][ni][2] * wt8);
                atomicAdd(&out[(size_t)tk8 * D_MODEL + c + 1], acc[mi][ni][3] * wt8);
            }
        }
    }
}

// ---------------- launch ----------------
extern "C" void kernel_launch(void* const* d_in, const int* in_sizes, int n_in,
                              void* d_out, int out_size) {
    const float* x    = (const float*)d_in[0];
    const int*   eidx = (const int*)  d_in[1];
    const float* ew   = (const float*)d_in[2];
    const float* w1   = (const float*)d_in[3];
    const float* w2   = (const float*)d_in[4];
    const float* w3   = (const float*)d_in[5];
    float* out = (float*)d_out;

    const int smem1 = (2 * A_STAGE_H + 4 * B_STAGE_H) * 2;   // 55296 B
    const int smem2 = (2 * A_STAGE_H + 2 * B_STAGE_H) * 2;   // 37888 B
    static int attr_done = 0;
    if (!attr_done) {
        cudaFuncSetAttribute(gemm1_kernel, cudaFuncAttributeMaxDynamicSharedMemorySize, smem1);
        cudaFuncSetAttribute(gemm2_kernel, cudaFuncAttributeMaxDynamicSharedMemorySize, smem2);
        attr_done = 1;
    }

    cvt_all_kernel<<<(unsigned)((CVT_UNITS + 255) / 256), 256>>>(
        (const float4*)w1, (const float4*)w2, (const float4*)w3, (const float4*)x, (float4*)out);
    scan_scatter_kernel<<<1, 256>>>(eidx, ew);

    gemm1_kernel<<<dim3(D_FF / BN, MAX_MTILES), 512, smem1>>>();
    gemm2_kernel<<<dim3(D_MODEL / BN, MAX_MTILES), 256, smem2>>>(out);
}